// round 1
// baseline (speedup 1.0000x reference)
#include <cuda_runtime.h>
#include <math.h>

#define LRELU_ALPHA 0.2f
#define MAXNB 256   // max neighbors per row; Binomial(4096,0.01) mean 41, std 6.4 -> 256 is >30 sigma

// ---------------- scratch (allocation-free: __device__ globals) ----------------
__device__ __align__(256) float g_Benc[1024 * 512];   // repacked encoder weight [f][h*64+d]
__device__ __align__(256) float g_Wh  [4096 * 512];   // Wh, [n][h*64+d]
__device__ __align__(256) float g_es  [8 * 4096];     // e_src [h][n]
__device__ __align__(256) float g_ed  [8 * 4096];     // e_dst [h][n]
__device__ __align__(256) float g_enc [4096 * 512];   // encoder output
__device__ __align__(256) float g_h1  [4096 * 256];
__device__ __align__(256) float g_h2  [4096 * 256];
__device__ __align__(256) float g_h3  [4096 * 512];

// ---------------- repack W[h][f][d] -> B[f][h*64+d] ----------------
__global__ void repack_kernel(const float* __restrict__ W, float* __restrict__ B) {
    int i = blockIdx.x * 256 + threadIdx.x;           // 524288 elements
    int f = i >> 9;
    int c = i & 511;
    int h = c >> 6;
    int d = c & 63;
    B[i] = W[h * 65536 + f * 64 + d];
}

// ---------------- generic tiled fp32 GEMM ----------------
// C[M,N] = act(A[M,K] @ B + bias), B either [K,N] (TRANSB=0) or [N,K] row-major -> A@B^T (TRANSB=1)
// BM=BN=64, BK=16, 256 threads, 4x4 micro-tile per thread. All dims are multiples of 64/16 here.
template <int TRANSB, int RELU>
__global__ __launch_bounds__(256) void gemm_kernel(
    const float* __restrict__ A, const float* __restrict__ B,
    const float* __restrict__ bias, float* __restrict__ C,
    int M, int N, int K)
{
    __shared__ float As[16][64];
    __shared__ float Bs[16][64];
    const int tid = threadIdx.x;
    const int tx = tid & 15;          // N direction
    const int ty = tid >> 4;          // M direction
    const int m0 = blockIdx.y * 64;
    const int n0 = blockIdx.x * 64;

    float acc[4][4] = {};

    for (int k0 = 0; k0 < K; k0 += 16) {
        // load A tile 64x16 (coalesced float4 along K), store transposed
        {
            int r  = tid >> 2;
            int kc = (tid & 3) * 4;
            float4 v = *(const float4*)(A + (size_t)(m0 + r) * K + k0 + kc);
            As[kc + 0][r] = v.x; As[kc + 1][r] = v.y;
            As[kc + 2][r] = v.z; As[kc + 3][r] = v.w;
        }
        if (TRANSB) {
            // B is [N,K] row-major; Bs[k][n] = B[n0+n][k0+k]
            int n  = tid >> 2;
            int kc = (tid & 3) * 4;
            float4 v = *(const float4*)(B + (size_t)(n0 + n) * K + k0 + kc);
            Bs[kc + 0][n] = v.x; Bs[kc + 1][n] = v.y;
            Bs[kc + 2][n] = v.z; Bs[kc + 3][n] = v.w;
        } else {
            // B is [K,N] row-major
            int kr = tid >> 4;
            int nc = (tid & 15) * 4;
            float4 v = *(const float4*)(B + (size_t)(k0 + kr) * N + n0 + nc);
            Bs[kr][nc + 0] = v.x; Bs[kr][nc + 1] = v.y;
            Bs[kr][nc + 2] = v.z; Bs[kr][nc + 3] = v.w;
        }
        __syncthreads();

        #pragma unroll
        for (int kk = 0; kk < 16; kk++) {
            float4 av = *(const float4*)&As[kk][ty * 4];
            float4 bv = *(const float4*)&Bs[kk][tx * 4];
            float a[4] = {av.x, av.y, av.z, av.w};
            float b[4] = {bv.x, bv.y, bv.z, bv.w};
            #pragma unroll
            for (int i = 0; i < 4; i++)
                #pragma unroll
                for (int j = 0; j < 4; j++)
                    acc[i][j] += a[i] * b[j];
        }
        __syncthreads();
    }

    #pragma unroll
    for (int i = 0; i < 4; i++) {
        int row = m0 + ty * 4 + i;
        #pragma unroll
        for (int j = 0; j < 4; j++) {
            int col = n0 + tx * 4 + j;
            float v = acc[i][j];
            if (bias) v += bias[col];
            if (RELU) v = fmaxf(v, 0.0f);
            C[(size_t)row * N + col] = v;
        }
    }
}

// ---------------- e_src / e_dst: per (n,h) dot of Wh row with a1/a2 ----------------
__global__ void esrc_kernel(const float* __restrict__ Wh,
                            const float* __restrict__ a1, const float* __restrict__ a2,
                            float* __restrict__ es, float* __restrict__ ed)
{
    int lane = threadIdx.x & 31;
    int h = threadIdx.x >> 5;      // 8 warps = 8 heads
    int n = blockIdx.x;            // 4096
    const float* wr = Wh + (size_t)n * 512 + h * 64;
    float w0 = wr[lane], w1 = wr[lane + 32];
    float s1 = w0 * a1[h * 64 + lane] + w1 * a1[h * 64 + lane + 32];
    float s2 = w0 * a2[h * 64 + lane] + w1 * a2[h * 64 + lane + 32];
    #pragma unroll
    for (int o = 16; o > 0; o >>= 1) {
        s1 += __shfl_xor_sync(0xffffffffu, s1, o);
        s2 += __shfl_xor_sync(0xffffffffu, s2, o);
    }
    if (lane == 0) {
        es[h * 4096 + n] = s1;
        ed[h * 4096 + n] = s2;
    }
}

// ---------------- sparse masked softmax attention + aggregate + elu ----------------
// One block per row n. Phase 1: deterministic (scan-based, no atomics) compaction of
// adj[n,:] nonzeros. Phase 2: warp h computes softmax over neighbors and aggregates
// Wh rows for its head, applies elu, writes enc[n][h*64+d].
__global__ __launch_bounds__(256) void attn_kernel(
    const float* __restrict__ adj, const float* __restrict__ Wh,
    const float* __restrict__ es,  const float* __restrict__ ed,
    float* __restrict__ enc)
{
    __shared__ int   s_idx[MAXNB];
    __shared__ float s_att[8][MAXNB];
    __shared__ int   s_wsum[8];
    __shared__ int   s_cnt;

    const int n    = blockIdx.x;
    const int t    = threadIdx.x;
    const int lane = t & 31;
    const int wid  = t >> 5;

    // ---- phase 1: compaction (each thread scans 4 float4s = 16 columns) ----
    int local[16];
    int lc = 0;
    const float4* row4 = (const float4*)(adj + (size_t)n * 4096);
    #pragma unroll
    for (int i = 0; i < 4; i++) {
        float4 v = row4[i * 256 + t];     // coalesced
        int c = (i * 256 + t) * 4;
        if (v.x > 0.0f) local[lc++] = c + 0;
        if (v.y > 0.0f) local[lc++] = c + 1;
        if (v.z > 0.0f) local[lc++] = c + 2;
        if (v.w > 0.0f) local[lc++] = c + 3;
    }
    // warp inclusive scan of lc
    int incl = lc;
    #pragma unroll
    for (int o = 1; o < 32; o <<= 1) {
        int v = __shfl_up_sync(0xffffffffu, incl, o);
        if (lane >= o) incl += v;
    }
    if (lane == 31) s_wsum[wid] = incl;
    __syncthreads();
    int wofs = 0;
    #pragma unroll
    for (int w = 0; w < 8; w++) if (w < wid) wofs += s_wsum[w];
    int pos = wofs + incl - lc;
    for (int j = 0; j < lc; j++)
        if (pos + j < MAXNB) s_idx[pos + j] = local[j];
    if (t == 255) s_cnt = wofs + incl;   // total nnz of this row
    __syncthreads();
    int cnt = s_cnt;
    if (cnt > MAXNB) cnt = MAXNB;        // unreachable for this distribution; safety only

    // ---- phase 2: per-head softmax over neighbors ----
    const int h   = wid;
    const float esv = es[h * 4096 + n];
    float mx = -1e30f;
    for (int m = lane; m < cnt; m += 32) {
        int j = s_idx[m];
        float z = esv + ed[h * 4096 + j];
        z = (z > 0.0f) ? z : LRELU_ALPHA * z;     // leaky_relu
        s_att[h][m] = z;
        mx = fmaxf(mx, z);
    }
    #pragma unroll
    for (int o = 16; o > 0; o >>= 1)
        mx = fmaxf(mx, __shfl_xor_sync(0xffffffffu, mx, o));
    __syncwarp();
    float sum = 0.0f;
    for (int m = lane; m < cnt; m += 32) {
        float p = __expf(s_att[h][m] - mx);
        s_att[h][m] = p;
        sum += p;
    }
    #pragma unroll
    for (int o = 16; o > 0; o >>= 1)
        sum += __shfl_xor_sync(0xffffffffu, sum, o);
    __syncwarp();
    float inv = 1.0f / sum;

    // ---- aggregate: each lane covers dims d=lane and d=lane+32 ----
    float acc0 = 0.0f, acc1 = 0.0f;
    for (int m = 0; m < cnt; m++) {
        int j   = s_idx[m];
        float a = s_att[h][m];
        const float* wr = Wh + (size_t)j * 512 + h * 64;
        acc0 += a * wr[lane];          // coalesced 128B per m
        acc1 += a * wr[lane + 32];
    }
    acc0 *= inv;
    acc1 *= inv;
    // elu
    acc0 = (acc0 > 0.0f) ? acc0 : (__expf(acc0) - 1.0f);
    acc1 = (acc1 > 0.0f) ? acc1 : (__expf(acc1) - 1.0f);
    enc[(size_t)n * 512 + h * 64 + lane]      = acc0;
    enc[(size_t)n * 512 + h * 64 + lane + 32] = acc1;
}

// ---------------- launch ----------------
extern "C" void kernel_launch(void* const* d_in, const int* in_sizes, int n_in,
                              void* d_out, int out_size)
{
    const float* x   = (const float*)d_in[0];
    const float* adj = (const float*)d_in[1];
    const float* W   = (const float*)d_in[2];
    const float* a1  = (const float*)d_in[3];
    const float* a2  = (const float*)d_in[4];
    const float* W1  = (const float*)d_in[5];
    const float* b1  = (const float*)d_in[6];
    const float* W2  = (const float*)d_in[7];
    const float* b2  = (const float*)d_in[8];
    const float* W3  = (const float*)d_in[9];
    const float* b3  = (const float*)d_in[10];
    const float* W4  = (const float*)d_in[11];
    const float* b4  = (const float*)d_in[12];
    float* out = (float*)d_out;

    float *Benc, *Wh, *es, *ed, *enc, *h1, *h2, *h3;
    cudaGetSymbolAddress((void**)&Benc, g_Benc);
    cudaGetSymbolAddress((void**)&Wh,   g_Wh);
    cudaGetSymbolAddress((void**)&es,   g_es);
    cudaGetSymbolAddress((void**)&ed,   g_ed);
    cudaGetSymbolAddress((void**)&enc,  g_enc);
    cudaGetSymbolAddress((void**)&h1,   g_h1);
    cudaGetSymbolAddress((void**)&h2,   g_h2);
    cudaGetSymbolAddress((void**)&h3,   g_h3);

    // encoder
    repack_kernel<<<2048, 256>>>(W, Benc);
    gemm_kernel<0, 0><<<dim3(8, 64),  256>>>(x,   Benc, nullptr, Wh, 4096, 512, 1024);
    esrc_kernel<<<4096, 256>>>(Wh, a1, a2, es, ed);
    attn_kernel<<<4096, 256>>>(adj, Wh, es, ed, enc);
    // decoder MLP
    gemm_kernel<1, 1><<<dim3(4, 64),  256>>>(enc, W1, b1, h1, 4096, 256,  512);
    gemm_kernel<1, 1><<<dim3(4, 64),  256>>>(h1,  W2, b2, h2, 4096, 256,  256);
    gemm_kernel<1, 1><<<dim3(8, 64),  256>>>(h2,  W3, b3, h3, 4096, 512,  256);
    gemm_kernel<1, 0><<<dim3(16, 64), 256>>>(h3,  W4, b4, out, 4096, 1024, 512);
}

// round 4
// speedup vs baseline: 1.1900x; 1.1900x over previous
#include <cuda_runtime.h>
#include <cuda_bf16.h>
#include <cstdint>
#include <math.h>

#define LRELU_ALPHA 0.2f
#define MAXNB 256

// ================= scratch (__device__ globals; no allocation) =================
__device__ __align__(256) __nv_bfloat16 g_xs  [4096 * 3072];  // x split  [hi|hi|lo]
__device__ __align__(256) __nv_bfloat16 g_Wes [512 * 3072];   // enc W split [hi|lo|hi], rows=h*64+d
__device__ __align__(256) float         g_Wh  [4096 * 512];
__device__ __align__(256) float         g_es  [8 * 4096];
__device__ __align__(256) float         g_ed  [8 * 4096];
__device__ __align__(256) __nv_bfloat16 g_encs[4096 * 1536];  // enc split [hi|hi|lo]
__device__ __align__(256) __nv_bfloat16 g_W1s [256 * 1536];
__device__ __align__(256) __nv_bfloat16 g_W2s [256 * 768];
__device__ __align__(256) __nv_bfloat16 g_W3s [512 * 768];
__device__ __align__(256) __nv_bfloat16 g_W4s [1024 * 1536];
__device__ __align__(256) __nv_bfloat16 g_h1s [4096 * 768];
__device__ __align__(256) __nv_bfloat16 g_h2s [4096 * 768];
__device__ __align__(256) __nv_bfloat16 g_h3s [4096 * 1536];

// ================= PTX helpers (plain sm_103-safe: no 'a' features) =================
__device__ __forceinline__ uint32_t smem_u32(const void* p) {
    uint32_t a;
    asm("{ .reg .u64 t; cvta.to.shared.u64 t, %1; cvt.u32.u64 %0, t; }" : "=r"(a) : "l"(p));
    return a;
}
__device__ __forceinline__ void cp16(uint32_t s, const void* g) {
    asm volatile("cp.async.cg.shared.global [%0], [%1], 16;" :: "r"(s), "l"(g));
}
__device__ __forceinline__ void cp_commit() {
    asm volatile("cp.async.commit_group;");
}
template <int N>
__device__ __forceinline__ void cp_wait() {
    asm volatile("cp.async.wait_group %0;" :: "n"(N));
}
__device__ __forceinline__ void ldsm4(uint32_t& r0, uint32_t& r1, uint32_t& r2, uint32_t& r3, uint32_t addr) {
    asm volatile("ldmatrix.sync.aligned.m8n8.x4.shared.b16 {%0,%1,%2,%3}, [%4];"
                 : "=r"(r0), "=r"(r1), "=r"(r2), "=r"(r3) : "r"(addr));
}
__device__ __forceinline__ void mma16816(float* d, const uint32_t* a, const uint32_t* b) {
    asm volatile(
        "mma.sync.aligned.m16n8k16.row.col.f32.bf16.bf16.f32 "
        "{%0,%1,%2,%3}, {%4,%5,%6,%7}, {%8,%9}, {%0,%1,%2,%3};"
        : "+f"(d[0]), "+f"(d[1]), "+f"(d[2]), "+f"(d[3])
        : "r"(a[0]), "r"(a[1]), "r"(a[2]), "r"(a[3]), "r"(b[0]), "r"(b[1]));
}

// ================= split/convert kernels =================
__global__ void split_A_kernel(const float* __restrict__ X, __nv_bfloat16* __restrict__ S, int M, int K) {
    int i = blockIdx.x * 256 + threadIdx.x;
    if (i >= M * K) return;
    int n = i / K, k = i - n * K;
    float v = X[i];
    __nv_bfloat16 hi = __float2bfloat16(v);
    __nv_bfloat16 lo = __float2bfloat16(v - __bfloat162float(hi));
    size_t b = (size_t)n * 3 * K;
    S[b + k] = hi; S[b + K + k] = hi; S[b + 2 * K + k] = lo;
}
__global__ void split_B_kernel(const float* __restrict__ W, __nv_bfloat16* __restrict__ S, int N, int K) {
    int i = blockIdx.x * 256 + threadIdx.x;
    if (i >= N * K) return;
    int n = i / K, k = i - n * K;
    float v = W[i];
    __nv_bfloat16 hi = __float2bfloat16(v);
    __nv_bfloat16 lo = __float2bfloat16(v - __bfloat162float(hi));
    size_t b = (size_t)n * 3 * K;
    S[b + k] = hi; S[b + K + k] = lo; S[b + 2 * K + k] = hi;
}
__global__ void repack_split_W_kernel(const float* __restrict__ W, __nv_bfloat16* __restrict__ S) {
    int i = blockIdx.x * 256 + threadIdx.x;   // 512*1024
    int n = i >> 10, f = i & 1023;
    int h = n >> 6, d = n & 63;
    float v = W[h * 65536 + f * 64 + d];
    __nv_bfloat16 hi = __float2bfloat16(v);
    __nv_bfloat16 lo = __float2bfloat16(v - __bfloat162float(hi));
    size_t b = (size_t)n * 3072;
    S[b + f] = hi; S[b + 1024 + f] = lo; S[b + 2048 + f] = hi;
}

// ================= mma.sync bf16 GEMM: C[M,N] = act(A' @ B'^T + bias) =================
// A' [M,Kp], B' [N,Kp] bf16 K-major, Kp multiple of 32. Tile 128x128, 8 warps,
// warp tile 64x32, BK=32, cp.async double buffer. Smem row stride 40 bf16 (80B:
// 16B-aligned for cp.async, conflict-free for ldmatrix).
#define SSTRIDE 40
template <int RELU, int WF32, int WSPLIT>
__global__ __launch_bounds__(256) void gemm_mma(
    const __nv_bfloat16* __restrict__ A, const __nv_bfloat16* __restrict__ B,
    const float* __restrict__ bias, float* __restrict__ Cf,
    __nv_bfloat16* __restrict__ Cs, int M, int N, int Kp)
{
    __shared__ __align__(16) __nv_bfloat16 sA[2][128 * SSTRIDE];
    __shared__ __align__(16) __nv_bfloat16 sB[2][128 * SSTRIDE];

    const int tid  = threadIdx.x;
    const int warp = tid >> 5;
    const int lane = tid & 31;
    const int m0 = blockIdx.y * 128;
    const int n0 = blockIdx.x * 128;
    const int wm = (warp & 1) * 64;        // warp m-offset within tile
    const int wn = (warp >> 1) * 32;       // warp n-offset within tile

    // per-thread load coordinates: 128 rows x 2 x 16B per matrix
    const int lrow = tid >> 1;             // 0..127
    const int lseg = (tid & 1) * 2;        // 0 or 2 (16B segments)

    float acc[4][4][4];
    #pragma unroll
    for (int i = 0; i < 4; i++)
        #pragma unroll
        for (int j = 0; j < 4; j++)
            #pragma unroll
            for (int k = 0; k < 4; k++) acc[i][j][k] = 0.0f;

    const int NC = Kp >> 5;

    // prefetch chunk 0
    {
        const __nv_bfloat16* ga = A + (size_t)(m0 + lrow) * Kp + lseg * 8;
        const __nv_bfloat16* gb = B + (size_t)(n0 + lrow) * Kp + lseg * 8;
        uint32_t da = smem_u32(&sA[0][lrow * SSTRIDE + lseg * 8]);
        uint32_t db = smem_u32(&sB[0][lrow * SSTRIDE + lseg * 8]);
        cp16(da, ga); cp16(da + 16, ga + 8);
        cp16(db, gb); cp16(db + 16, gb + 8);
        cp_commit();
    }

    for (int c = 0; c < NC; c++) {
        const int buf = c & 1;
        if (c + 1 < NC) {
            const __nv_bfloat16* ga = A + (size_t)(m0 + lrow) * Kp + (c + 1) * 32 + lseg * 8;
            const __nv_bfloat16* gb = B + (size_t)(n0 + lrow) * Kp + (c + 1) * 32 + lseg * 8;
            uint32_t da = smem_u32(&sA[buf ^ 1][lrow * SSTRIDE + lseg * 8]);
            uint32_t db = smem_u32(&sB[buf ^ 1][lrow * SSTRIDE + lseg * 8]);
            cp16(da, ga); cp16(da + 16, ga + 8);
            cp16(db, gb); cp16(db + 16, gb + 8);
            cp_commit();
            cp_wait<1>();
        } else {
            cp_wait<0>();
        }
        __syncthreads();

        #pragma unroll
        for (int ks = 0; ks < 2; ks++) {
            // A fragments: 4 m16 tiles
            uint32_t af[4][4];
            #pragma unroll
            for (int mi = 0; mi < 4; mi++) {
                uint32_t addr = smem_u32(&sA[buf][(wm + mi * 16 + (lane & 15)) * SSTRIDE
                                                  + ks * 16 + (lane >> 4) * 8]);
                ldsm4(af[mi][0], af[mi][1], af[mi][2], af[mi][3], addr);
            }
            // B fragments: 4 n8 tiles (two x4 loads over 16-row n-groups)
            uint32_t bf[4][2];
            #pragma unroll
            for (int ng = 0; ng < 2; ng++) {
                uint32_t r0, r1, r2, r3;
                uint32_t addr = smem_u32(&sB[buf][(wn + ng * 16 + (lane & 15)) * SSTRIDE
                                                  + ks * 16 + (lane >> 4) * 8]);
                ldsm4(r0, r1, r2, r3, addr);
                bf[ng * 2 + 0][0] = r0; bf[ng * 2 + 0][1] = r2;   // rows n0-7: k0-7, k8-15
                bf[ng * 2 + 1][0] = r1; bf[ng * 2 + 1][1] = r3;   // rows n8-15
            }
            #pragma unroll
            for (int mi = 0; mi < 4; mi++)
                #pragma unroll
                for (int nj = 0; nj < 4; nj++)
                    mma16816(acc[mi][nj], af[mi], bf[nj]);
        }
        __syncthreads();
    }

    // ---- epilogue ----
    const int g = lane >> 2, t = lane & 3;
    #pragma unroll
    for (int mi = 0; mi < 4; mi++) {
        #pragma unroll
        for (int nj = 0; nj < 4; nj++) {
            int gr0 = m0 + wm + mi * 16 + g;
            int gc0 = n0 + wn + nj * 8 + 2 * t;
            #pragma unroll
            for (int hh = 0; hh < 2; hh++) {       // row g / g+8
                int gm = gr0 + hh * 8;
                #pragma unroll
                for (int ww = 0; ww < 2; ww++) {   // col 2t / 2t+1
                    int gc = gc0 + ww;
                    float v = acc[mi][nj][hh * 2 + ww];
                    if (bias) v += bias[gc];
                    if (RELU) v = fmaxf(v, 0.0f);
                    if (WF32) Cf[(size_t)gm * N + gc] = v;
                    if (WSPLIT) {
                        __nv_bfloat16 hi = __float2bfloat16(v);
                        __nv_bfloat16 lo = __float2bfloat16(v - __bfloat162float(hi));
                        size_t bo = (size_t)gm * 3 * N;
                        Cs[bo + gc] = hi; Cs[bo + N + gc] = hi; Cs[bo + 2 * N + gc] = lo;
                    }
                }
            }
        }
    }
}

// ================= e_src / e_dst =================
__global__ void esrc_kernel(const float* __restrict__ Wh,
                            const float* __restrict__ a1, const float* __restrict__ a2,
                            float* __restrict__ es, float* __restrict__ ed)
{
    int lane = threadIdx.x & 31;
    int h = threadIdx.x >> 5;
    int n = blockIdx.x;
    const float* wr = Wh + (size_t)n * 512 + h * 64;
    float w0 = wr[lane], w1 = wr[lane + 32];
    float s1 = w0 * a1[h * 64 + lane] + w1 * a1[h * 64 + lane + 32];
    float s2 = w0 * a2[h * 64 + lane] + w1 * a2[h * 64 + lane + 32];
    #pragma unroll
    for (int o = 16; o > 0; o >>= 1) {
        s1 += __shfl_xor_sync(0xffffffffu, s1, o);
        s2 += __shfl_xor_sync(0xffffffffu, s2, o);
    }
    if (lane == 0) { es[h * 4096 + n] = s1; ed[h * 4096 + n] = s2; }
}

// ================= sparse softmax attention + aggregate + elu (+split write) =================
__global__ __launch_bounds__(256) void attn_kernel(
    const float* __restrict__ adj, const float* __restrict__ Wh,
    const float* __restrict__ es,  const float* __restrict__ ed,
    __nv_bfloat16* __restrict__ encs)
{
    __shared__ int   s_idx[MAXNB];
    __shared__ float s_att[8][MAXNB];
    __shared__ int   s_wsum[8];
    __shared__ int   s_cnt;

    const int n    = blockIdx.x;
    const int t    = threadIdx.x;
    const int lane = t & 31;
    const int wid  = t >> 5;

    int local[16];
    int lc = 0;
    const float4* row4 = (const float4*)(adj + (size_t)n * 4096);
    #pragma unroll
    for (int i = 0; i < 4; i++) {
        float4 v = row4[i * 256 + t];
        int c = (i * 256 + t) * 4;
        if (v.x > 0.0f) local[lc++] = c + 0;
        if (v.y > 0.0f) local[lc++] = c + 1;
        if (v.z > 0.0f) local[lc++] = c + 2;
        if (v.w > 0.0f) local[lc++] = c + 3;
    }
    int incl = lc;
    #pragma unroll
    for (int o = 1; o < 32; o <<= 1) {
        int v = __shfl_up_sync(0xffffffffu, incl, o);
        if (lane >= o) incl += v;
    }
    if (lane == 31) s_wsum[wid] = incl;
    __syncthreads();
    int wofs = 0;
    #pragma unroll
    for (int w = 0; w < 8; w++) if (w < wid) wofs += s_wsum[w];
    int pos = wofs + incl - lc;
    for (int j = 0; j < lc; j++)
        if (pos + j < MAXNB) s_idx[pos + j] = local[j];
    if (t == 255) s_cnt = wofs + incl;
    __syncthreads();
    int cnt = s_cnt;
    if (cnt > MAXNB) cnt = MAXNB;

    const int h = wid;
    const float esv = es[h * 4096 + n];
    float mx = -1e30f;
    for (int m = lane; m < cnt; m += 32) {
        int j = s_idx[m];
        float z = esv + ed[h * 4096 + j];
        z = (z > 0.0f) ? z : LRELU_ALPHA * z;
        s_att[h][m] = z;
        mx = fmaxf(mx, z);
    }
    #pragma unroll
    for (int o = 16; o > 0; o >>= 1)
        mx = fmaxf(mx, __shfl_xor_sync(0xffffffffu, mx, o));
    __syncwarp();
    float sum = 0.0f;
    for (int m = lane; m < cnt; m += 32) {
        float p = __expf(s_att[h][m] - mx);
        s_att[h][m] = p;
        sum += p;
    }
    #pragma unroll
    for (int o = 16; o > 0; o >>= 1)
        sum += __shfl_xor_sync(0xffffffffu, sum, o);
    __syncwarp();
    float inv = 1.0f / sum;

    float acc0 = 0.0f, acc1 = 0.0f;
    for (int m = 0; m < cnt; m++) {
        int j   = s_idx[m];
        float a = s_att[h][m];
        const float* wr = Wh + (size_t)j * 512 + h * 64;
        acc0 += a * wr[lane];
        acc1 += a * wr[lane + 32];
    }
    acc0 *= inv;
    acc1 *= inv;
    acc0 = (acc0 > 0.0f) ? acc0 : (__expf(acc0) - 1.0f);
    acc1 = (acc1 > 0.0f) ? acc1 : (__expf(acc1) - 1.0f);

    // write split layout [hi|hi|lo], K = 512
    size_t bo = (size_t)n * 1536;
    int c0 = h * 64 + lane, c1 = c0 + 32;
    __nv_bfloat16 h0 = __float2bfloat16(acc0);
    __nv_bfloat16 l0 = __float2bfloat16(acc0 - __bfloat162float(h0));
    __nv_bfloat16 h1 = __float2bfloat16(acc1);
    __nv_bfloat16 l1 = __float2bfloat16(acc1 - __bfloat162float(h1));
    encs[bo + c0] = h0;        encs[bo + c1] = h1;
    encs[bo + 512 + c0] = h0;  encs[bo + 512 + c1] = h1;
    encs[bo + 1024 + c0] = l0; encs[bo + 1024 + c1] = l1;
}

// ================= launch =================
extern "C" void kernel_launch(void* const* d_in, const int* in_sizes, int n_in,
                              void* d_out, int out_size)
{
    const float* x   = (const float*)d_in[0];
    const float* adj = (const float*)d_in[1];
    const float* W   = (const float*)d_in[2];
    const float* a1  = (const float*)d_in[3];
    const float* a2  = (const float*)d_in[4];
    const float* W1  = (const float*)d_in[5];
    const float* b1  = (const float*)d_in[6];
    const float* W2  = (const float*)d_in[7];
    const float* b2  = (const float*)d_in[8];
    const float* W3  = (const float*)d_in[9];
    const float* b3  = (const float*)d_in[10];
    const float* W4  = (const float*)d_in[11];
    const float* b4  = (const float*)d_in[12];
    float* out = (float*)d_out;

    __nv_bfloat16 *xs, *Wes, *encs, *W1s, *W2s, *W3s, *W4s, *h1s, *h2s, *h3s;
    float *Wh, *es, *ed;
    cudaGetSymbolAddress((void**)&xs, g_xs);
    cudaGetSymbolAddress((void**)&Wes, g_Wes);
    cudaGetSymbolAddress((void**)&Wh, g_Wh);
    cudaGetSymbolAddress((void**)&es, g_es);
    cudaGetSymbolAddress((void**)&ed, g_ed);
    cudaGetSymbolAddress((void**)&encs, g_encs);
    cudaGetSymbolAddress((void**)&W1s, g_W1s);
    cudaGetSymbolAddress((void**)&W2s, g_W2s);
    cudaGetSymbolAddress((void**)&W3s, g_W3s);
    cudaGetSymbolAddress((void**)&W4s, g_W4s);
    cudaGetSymbolAddress((void**)&h1s, g_h1s);
    cudaGetSymbolAddress((void**)&h2s, g_h2s);
    cudaGetSymbolAddress((void**)&h3s, g_h3s);

    // conversions
    split_A_kernel<<<(4096 * 1024 + 255) / 256, 256>>>(x, xs, 4096, 1024);
    repack_split_W_kernel<<<(512 * 1024) / 256, 256>>>(W, Wes);
    split_B_kernel<<<(256 * 512 + 255) / 256, 256>>>(W1, W1s, 256, 512);
    split_B_kernel<<<(256 * 256 + 255) / 256, 256>>>(W2, W2s, 256, 256);
    split_B_kernel<<<(512 * 256 + 255) / 256, 256>>>(W3, W3s, 512, 256);
    split_B_kernel<<<(1024 * 512 + 255) / 256, 256>>>(W4, W4s, 1024, 512);

    // encoder GEMM: Wh = x @ Wenc   (M=4096, N=512, Kp=3072)
    gemm_mma<0, 1, 0><<<dim3(4, 32), 256>>>(xs, Wes, nullptr, Wh, nullptr, 4096, 512, 3072);
    esrc_kernel<<<4096, 256>>>(Wh, a1, a2, es, ed);
    attn_kernel<<<4096, 256>>>(adj, Wh, es, ed, encs);

    // decoder
    gemm_mma<1, 0, 1><<<dim3(2, 32), 256>>>(encs, W1s, b1, nullptr, h1s, 4096, 256, 1536);
    gemm_mma<1, 0, 1><<<dim3(2, 32), 256>>>(h1s,  W2s, b2, nullptr, h2s, 4096, 256, 768);
    gemm_mma<1, 0, 1><<<dim3(4, 32), 256>>>(h2s,  W3s, b3, nullptr, h3s, 4096, 512, 768);
    gemm_mma<0, 1, 0><<<dim3(8, 32), 256>>>(h3s,  W4s, b4, out, nullptr, 4096, 1024, 1536);
}

// round 6
// speedup vs baseline: 1.5642x; 1.3145x over previous
#include <cuda_runtime.h>
#include <cuda_bf16.h>
#include <cstdint>
#include <math.h>

#define LRELU_ALPHA 0.2f
#define MAXNB 256

// ================= scratch (__device__ globals; no allocation) =================
__device__ __align__(256) __nv_bfloat16 g_xs  [4096 * 3072];  // x split  [hi|hi|lo]
__device__ __align__(256) __nv_bfloat16 g_Wes [512 * 3072];   // enc W split [hi|lo|hi]
__device__ __align__(256) float         g_Wh  [4096 * 512];
__device__ __align__(256) float         g_es  [8 * 4096];
__device__ __align__(256) float         g_ed  [8 * 4096];
__device__ __align__(256) __nv_bfloat16 g_encs[4096 * 1536];
__device__ __align__(256) __nv_bfloat16 g_W1s [256 * 1536];
__device__ __align__(256) __nv_bfloat16 g_W2s [256 * 768];
__device__ __align__(256) __nv_bfloat16 g_W3s [512 * 768];
__device__ __align__(256) __nv_bfloat16 g_W4s [1024 * 1536];
__device__ __align__(256) __nv_bfloat16 g_h1s [4096 * 768];
__device__ __align__(256) __nv_bfloat16 g_h2s [4096 * 768];
__device__ __align__(256) __nv_bfloat16 g_h3s [4096 * 1536];

// ================= PTX helpers (plain sm_103-safe) =================
__device__ __forceinline__ uint32_t smem_u32(const void* p) {
    uint32_t a;
    asm("{ .reg .u64 t; cvta.to.shared.u64 t, %1; cvt.u32.u64 %0, t; }" : "=r"(a) : "l"(p));
    return a;
}
__device__ __forceinline__ void cp16(uint32_t s, const void* g) {
    asm volatile("cp.async.cg.shared.global [%0], [%1], 16;" :: "r"(s), "l"(g));
}
__device__ __forceinline__ void cp_commit() {
    asm volatile("cp.async.commit_group;");
}
template <int N>
__device__ __forceinline__ void cp_wait() {
    asm volatile("cp.async.wait_group %0;" :: "n"(N));
}
__device__ __forceinline__ void ldsm4(uint32_t& r0, uint32_t& r1, uint32_t& r2, uint32_t& r3, uint32_t addr) {
    asm volatile("ldmatrix.sync.aligned.m8n8.x4.shared.b16 {%0,%1,%2,%3}, [%4];"
                 : "=r"(r0), "=r"(r1), "=r"(r2), "=r"(r3) : "r"(addr));
}
__device__ __forceinline__ void mma16816(float* d, const uint32_t* a, const uint32_t* b) {
    asm volatile(
        "mma.sync.aligned.m16n8k16.row.col.f32.bf16.bf16.f32 "
        "{%0,%1,%2,%3}, {%4,%5,%6,%7}, {%8,%9}, {%0,%1,%2,%3};"
        : "+f"(d[0]), "+f"(d[1]), "+f"(d[2]), "+f"(d[3])
        : "r"(a[0]), "r"(a[1]), "r"(a[2]), "r"(a[3]), "r"(b[0]), "r"(b[1]));
}

// ================= split/convert kernels =================
__global__ void split_A_kernel(const float* __restrict__ X, __nv_bfloat16* __restrict__ S, int M, int K) {
    int i = blockIdx.x * 256 + threadIdx.x;
    if (i >= M * K) return;
    int n = i / K, k = i - n * K;
    float v = X[i];
    __nv_bfloat16 hi = __float2bfloat16(v);
    __nv_bfloat16 lo = __float2bfloat16(v - __bfloat162float(hi));
    size_t b = (size_t)n * 3 * K;
    S[b + k] = hi; S[b + K + k] = hi; S[b + 2 * K + k] = lo;
}
__global__ void split_B_kernel(const float* __restrict__ W, __nv_bfloat16* __restrict__ S, int N, int K) {
    int i = blockIdx.x * 256 + threadIdx.x;
    if (i >= N * K) return;
    int n = i / K, k = i - n * K;
    float v = W[i];
    __nv_bfloat16 hi = __float2bfloat16(v);
    __nv_bfloat16 lo = __float2bfloat16(v - __bfloat162float(hi));
    size_t b = (size_t)n * 3 * K;
    S[b + k] = hi; S[b + K + k] = lo; S[b + 2 * K + k] = hi;
}
__global__ void repack_split_W_kernel(const float* __restrict__ W, __nv_bfloat16* __restrict__ S) {
    int i = blockIdx.x * 256 + threadIdx.x;   // 512*1024
    int n = i >> 10, f = i & 1023;
    int h = n >> 6, d = n & 63;
    float v = W[h * 65536 + f * 64 + d];
    __nv_bfloat16 hi = __float2bfloat16(v);
    __nv_bfloat16 lo = __float2bfloat16(v - __bfloat162float(hi));
    size_t b = (size_t)n * 3072;
    S[b + f] = hi; S[b + 1024 + f] = lo; S[b + 2048 + f] = hi;
}

// ================= mma.sync bf16 GEMM, 3-stage cp.async, swizzled smem ===========
// C[M,N] = act(A'[M,Kp] @ B'[N,Kp]^T + bias). Tile TM x 128, 8 warps, BK=32.
// Smem: 64B rows (32 bf16), XOR swizzle phys_kseg = kseg ^ ((row>>1)&3) keeps
// ldmatrix conflict-free without padding. All static; T128 uses exactly 48KB.
template <int TM, int RELU, int WF32, int WSPLIT>
__global__ __launch_bounds__(256) void gemm_mma(
    const __nv_bfloat16* __restrict__ A, const __nv_bfloat16* __restrict__ B,
    const float* __restrict__ bias, float* __restrict__ Cf,
    __nv_bfloat16* __restrict__ Cs, int M, int N, int Kp)
{
    __shared__ __align__(16) __nv_bfloat16 sAb[3 * TM * 32];
    __shared__ __align__(16) __nv_bfloat16 sBb[3 * 128 * 32];

    constexpr int MI = TM / 32;
    const int tid  = threadIdx.x;
    const int warp = tid >> 5;
    const int lane = tid & 31;
    const int m0 = blockIdx.y * TM;
    const int n0 = blockIdx.x * 128;
    const int wm = (warp & 1) * (TM / 2);
    const int wn = (warp >> 1) * 32;
    const uint32_t baseA = smem_u32(sAb);
    const uint32_t baseB = smem_u32(sBb);

    float acc[MI][4][4];
    #pragma unroll
    for (int i = 0; i < MI; i++)
        #pragma unroll
        for (int j = 0; j < 4; j++)
            #pragma unroll
            for (int k = 0; k < 4; k++) acc[i][j][k] = 0.0f;

    const int NC = Kp >> 5;

    auto load_chunk = [&](int c, int s) {
        // B: 128 rows x 32 cols; each thread: row=tid>>1, two 16B segs
        {
            int r = tid >> 1, kb = (tid & 1) * 2;
            const __nv_bfloat16* gb = B + (size_t)(n0 + r) * Kp + c * 32;
            uint32_t rowbase = baseB + s * 128 * 64 + r * 64;
            uint32_t sw = ((r >> 1) & 3);
            cp16(rowbase + ((kb    ) ^ sw) * 16, gb + kb * 8);
            cp16(rowbase + ((kb + 1) ^ sw) * 16, gb + (kb + 1) * 8);
        }
        if (TM == 128) {
            int r = tid >> 1, kb = (tid & 1) * 2;
            const __nv_bfloat16* ga = A + (size_t)(m0 + r) * Kp + c * 32;
            uint32_t rowbase = baseA + s * TM * 64 + r * 64;
            uint32_t sw = ((r >> 1) & 3);
            cp16(rowbase + ((kb    ) ^ sw) * 16, ga + kb * 8);
            cp16(rowbase + ((kb + 1) ^ sw) * 16, ga + (kb + 1) * 8);
        } else {
            int r = tid >> 2, ks = tid & 3;
            const __nv_bfloat16* ga = A + (size_t)(m0 + r) * Kp + c * 32;
            uint32_t rowbase = baseA + s * TM * 64 + r * 64;
            cp16(rowbase + (ks ^ ((r >> 1) & 3)) * 16, ga + ks * 8);
        }
    };

    // prologue: chunks 0,1 into stages 0,1
    load_chunk(0, 0); cp_commit();
    load_chunk(1, 1); cp_commit();

    for (int c = 0; c < NC; c++) {
        const int st = c % 3;
        cp_wait<1>();            // chunk c complete
        __syncthreads();
        if (c + 2 < NC) load_chunk(c + 2, (c + 2) % 3);
        cp_commit();             // uniform group accounting (empty groups OK)

        #pragma unroll
        for (int ks = 0; ks < 2; ks++) {
            uint32_t af[MI][4];
            #pragma unroll
            for (int mi = 0; mi < MI; mi++) {
                int row = wm + mi * 16 + (lane & 15);
                int kseg = ks * 2 + (lane >> 4);
                uint32_t addr = baseA + st * TM * 64 + row * 64
                              + (kseg ^ ((row >> 1) & 3)) * 16;
                ldsm4(af[mi][0], af[mi][1], af[mi][2], af[mi][3], addr);
            }
            uint32_t bf[4][2];
            #pragma unroll
            for (int ng = 0; ng < 2; ng++) {
                uint32_t r0, r1, r2, r3;
                int row = wn + ng * 16 + (lane & 15);
                int kseg = ks * 2 + (lane >> 4);
                uint32_t addr = baseB + st * 128 * 64 + row * 64
                              + (kseg ^ ((row >> 1) & 3)) * 16;
                ldsm4(r0, r1, r2, r3, addr);
                bf[ng * 2 + 0][0] = r0; bf[ng * 2 + 0][1] = r2;
                bf[ng * 2 + 1][0] = r1; bf[ng * 2 + 1][1] = r3;
            }
            #pragma unroll
            for (int mi = 0; mi < MI; mi++)
                #pragma unroll
                for (int nj = 0; nj < 4; nj++)
                    mma16816(acc[mi][nj], af[mi], bf[nj]);
        }
    }

    // ---- epilogue ----
    const int g = lane >> 2, t = lane & 3;
    #pragma unroll
    for (int mi = 0; mi < MI; mi++) {
        #pragma unroll
        for (int nj = 0; nj < 4; nj++) {
            int gr0 = m0 + wm + mi * 16 + g;
            int gc0 = n0 + wn + nj * 8 + 2 * t;
            #pragma unroll
            for (int hh = 0; hh < 2; hh++) {
                int gm = gr0 + hh * 8;
                #pragma unroll
                for (int ww = 0; ww < 2; ww++) {
                    int gc = gc0 + ww;
                    float v = acc[mi][nj][hh * 2 + ww];
                    if (bias) v += bias[gc];
                    if (RELU) v = fmaxf(v, 0.0f);
                    if (WF32) Cf[(size_t)gm * N + gc] = v;
                    if (WSPLIT) {
                        __nv_bfloat16 hi = __float2bfloat16(v);
                        __nv_bfloat16 lo = __float2bfloat16(v - __bfloat162float(hi));
                        size_t bo = (size_t)gm * 3 * N;
                        Cs[bo + gc] = hi; Cs[bo + N + gc] = hi; Cs[bo + 2 * N + gc] = lo;
                    }
                }
            }
        }
    }
}

// ================= e_src / e_dst =================
__global__ void esrc_kernel(const float* __restrict__ Wh,
                            const float* __restrict__ a1, const float* __restrict__ a2,
                            float* __restrict__ es, float* __restrict__ ed)
{
    int lane = threadIdx.x & 31;
    int h = threadIdx.x >> 5;
    int n = blockIdx.x;
    const float* wr = Wh + (size_t)n * 512 + h * 64;
    float w0 = wr[lane], w1 = wr[lane + 32];
    float s1 = w0 * a1[h * 64 + lane] + w1 * a1[h * 64 + lane + 32];
    float s2 = w0 * a2[h * 64 + lane] + w1 * a2[h * 64 + lane + 32];
    #pragma unroll
    for (int o = 16; o > 0; o >>= 1) {
        s1 += __shfl_xor_sync(0xffffffffu, s1, o);
        s2 += __shfl_xor_sync(0xffffffffu, s2, o);
    }
    if (lane == 0) { es[h * 4096 + n] = s1; ed[h * 4096 + n] = s2; }
}

// ================= sparse softmax attention + aggregate + elu (+split write) =================
__global__ __launch_bounds__(256) void attn_kernel(
    const float* __restrict__ adj, const float* __restrict__ Wh,
    const float* __restrict__ es,  const float* __restrict__ ed,
    __nv_bfloat16* __restrict__ encs)
{
    __shared__ int   s_idx[MAXNB];
    __shared__ float s_att[8][MAXNB];
    __shared__ int   s_wsum[8];
    __shared__ int   s_cnt;

    const int n    = blockIdx.x;
    const int t    = threadIdx.x;
    const int lane = t & 31;
    const int wid  = t >> 5;

    int local[16];
    int lc = 0;
    const float4* row4 = (const float4*)(adj + (size_t)n * 4096);
    #pragma unroll
    for (int i = 0; i < 4; i++) {
        float4 v = row4[i * 256 + t];
        int c = (i * 256 + t) * 4;
        if (v.x > 0.0f) local[lc++] = c + 0;
        if (v.y > 0.0f) local[lc++] = c + 1;
        if (v.z > 0.0f) local[lc++] = c + 2;
        if (v.w > 0.0f) local[lc++] = c + 3;
    }
    int incl = lc;
    #pragma unroll
    for (int o = 1; o < 32; o <<= 1) {
        int v = __shfl_up_sync(0xffffffffu, incl, o);
        if (lane >= o) incl += v;
    }
    if (lane == 31) s_wsum[wid] = incl;
    __syncthreads();
    int wofs = 0;
    #pragma unroll
    for (int w = 0; w < 8; w++) if (w < wid) wofs += s_wsum[w];
    int pos = wofs + incl - lc;
    for (int j = 0; j < lc; j++)
        if (pos + j < MAXNB) s_idx[pos + j] = local[j];
    if (t == 255) s_cnt = wofs + incl;
    __syncthreads();
    int cnt = s_cnt;
    if (cnt > MAXNB) cnt = MAXNB;

    const int h = wid;
    const float esv = es[h * 4096 + n];
    float mx = -1e30f;
    for (int m = lane; m < cnt; m += 32) {
        int j = s_idx[m];
        float z = esv + ed[h * 4096 + j];
        z = (z > 0.0f) ? z : LRELU_ALPHA * z;
        s_att[h][m] = z;
        mx = fmaxf(mx, z);
    }
    #pragma unroll
    for (int o = 16; o > 0; o >>= 1)
        mx = fmaxf(mx, __shfl_xor_sync(0xffffffffu, mx, o));
    __syncwarp();
    float sum = 0.0f;
    for (int m = lane; m < cnt; m += 32) {
        float p = __expf(s_att[h][m] - mx);
        s_att[h][m] = p;
        sum += p;
    }
    #pragma unroll
    for (int o = 16; o > 0; o >>= 1)
        sum += __shfl_xor_sync(0xffffffffu, sum, o);
    __syncwarp();
    float inv = 1.0f / sum;

    float acc0 = 0.0f, acc1 = 0.0f;
    for (int m = 0; m < cnt; m++) {
        int j   = s_idx[m];
        float a = s_att[h][m];
        const float* wr = Wh + (size_t)j * 512 + h * 64;
        acc0 += a * wr[lane];
        acc1 += a * wr[lane + 32];
    }
    acc0 *= inv;
    acc1 *= inv;
    acc0 = (acc0 > 0.0f) ? acc0 : (__expf(acc0) - 1.0f);
    acc1 = (acc1 > 0.0f) ? acc1 : (__expf(acc1) - 1.0f);

    size_t bo = (size_t)n * 1536;
    int c0 = h * 64 + lane, c1 = c0 + 32;
    __nv_bfloat16 h0 = __float2bfloat16(acc0);
    __nv_bfloat16 l0 = __float2bfloat16(acc0 - __bfloat162float(h0));
    __nv_bfloat16 h1 = __float2bfloat16(acc1);
    __nv_bfloat16 l1 = __float2bfloat16(acc1 - __bfloat162float(h1));
    encs[bo + c0] = h0;        encs[bo + c1] = h1;
    encs[bo + 512 + c0] = h0;  encs[bo + 512 + c1] = h1;
    encs[bo + 1024 + c0] = l0; encs[bo + 1024 + c1] = l1;
}

// ================= launch (nothing but kernel launches + symbol lookups) =========
extern "C" void kernel_launch(void* const* d_in, const int* in_sizes, int n_in,
                              void* d_out, int out_size)
{
    const float* x   = (const float*)d_in[0];
    const float* adj = (const float*)d_in[1];
    const float* W   = (const float*)d_in[2];
    const float* a1  = (const float*)d_in[3];
    const float* a2  = (const float*)d_in[4];
    const float* W1  = (const float*)d_in[5];
    const float* b1  = (const float*)d_in[6];
    const float* W2  = (const float*)d_in[7];
    const float* b2  = (const float*)d_in[8];
    const float* W3  = (const float*)d_in[9];
    const float* b3  = (const float*)d_in[10];
    const float* W4  = (const float*)d_in[11];
    const float* b4  = (const float*)d_in[12];
    float* out = (float*)d_out;

    __nv_bfloat16 *xs, *Wes, *encs, *W1s, *W2s, *W3s, *W4s, *h1s, *h2s, *h3s;
    float *Wh, *es, *ed;
    cudaGetSymbolAddress((void**)&xs, g_xs);
    cudaGetSymbolAddress((void**)&Wes, g_Wes);
    cudaGetSymbolAddress((void**)&Wh, g_Wh);
    cudaGetSymbolAddress((void**)&es, g_es);
    cudaGetSymbolAddress((void**)&ed, g_ed);
    cudaGetSymbolAddress((void**)&encs, g_encs);
    cudaGetSymbolAddress((void**)&W1s, g_W1s);
    cudaGetSymbolAddress((void**)&W2s, g_W2s);
    cudaGetSymbolAddress((void**)&W3s, g_W3s);
    cudaGetSymbolAddress((void**)&W4s, g_W4s);
    cudaGetSymbolAddress((void**)&h1s, g_h1s);
    cudaGetSymbolAddress((void**)&h2s, g_h2s);
    cudaGetSymbolAddress((void**)&h3s, g_h3s);

    // conversions
    split_A_kernel<<<(4096 * 1024 + 255) / 256, 256>>>(x, xs, 4096, 1024);
    repack_split_W_kernel<<<(512 * 1024) / 256, 256>>>(W, Wes);
    split_B_kernel<<<(256 * 512 + 255) / 256, 256>>>(W1, W1s, 256, 512);
    split_B_kernel<<<(256 * 256 + 255) / 256, 256>>>(W2, W2s, 256, 256);
    split_B_kernel<<<(512 * 256 + 255) / 256, 256>>>(W3, W3s, 512, 256);
    split_B_kernel<<<(1024 * 512 + 255) / 256, 256>>>(W4, W4s, 1024, 512);

    // encoder GEMM: Wh = x @ Wenc   (M=4096, N=512, Kp=3072)
    gemm_mma<128, 0, 1, 0><<<dim3(4, 32), 256>>>(xs, Wes, nullptr, Wh, nullptr, 4096, 512, 3072);
    esrc_kernel<<<4096, 256>>>(Wh, a1, a2, es, ed);
    attn_kernel<<<4096, 256>>>(adj, Wh, es, ed, encs);

    // decoder
    gemm_mma<64, 1, 0, 1><<<dim3(2, 64), 256>>>(encs, W1s, b1, nullptr, h1s, 4096, 256, 1536);
    gemm_mma<64, 1, 0, 1><<<dim3(2, 64), 256>>>(h1s,  W2s, b2, nullptr, h2s, 4096, 256, 768);
    gemm_mma<128, 1, 0, 1><<<dim3(4, 32), 256>>>(h2s, W3s, b3, nullptr, h3s, 4096, 512, 768);
    gemm_mma<128, 0, 1, 0><<<dim3(8, 32), 256>>>(h3s, W4s, b4, out, nullptr, 4096, 1024, 1536);
}

// round 7
// speedup vs baseline: 1.6269x; 1.0401x over previous
#include <cuda_runtime.h>
#include <cuda_bf16.h>
#include <cstdint>
#include <math.h>

#define LRELU_ALPHA 0.2f
#define MAXNB 256

// ================= scratch (__device__ globals; no allocation) =================
__device__ __align__(256) __nv_bfloat16 g_xs  [4096 * 3072];  // x split  [hi|hi|lo]
__device__ __align__(256) __nv_bfloat16 g_Wes [512 * 3072];   // enc W split [hi|lo|hi]
__device__ __align__(256) float         g_Wh  [4096 * 512];
__device__ __align__(256) float         g_es  [8 * 4096];
__device__ __align__(256) float         g_ed  [8 * 4096];
__device__ __align__(256) __nv_bfloat16 g_encs[4096 * 1536];
__device__ __align__(256) __nv_bfloat16 g_W1s [256 * 1536];
__device__ __align__(256) __nv_bfloat16 g_W2s [256 * 768];
__device__ __align__(256) __nv_bfloat16 g_W3s [512 * 768];
__device__ __align__(256) __nv_bfloat16 g_W4s [1024 * 1536];
__device__ __align__(256) __nv_bfloat16 g_h1s [4096 * 768];
__device__ __align__(256) __nv_bfloat16 g_h2s [4096 * 768];
__device__ __align__(256) __nv_bfloat16 g_h3s [4096 * 1536];

// ================= PTX helpers (plain sm_103-safe) =================
__device__ __forceinline__ uint32_t smem_u32(const void* p) {
    uint32_t a;
    asm("{ .reg .u64 t; cvta.to.shared.u64 t, %1; cvt.u32.u64 %0, t; }" : "=r"(a) : "l"(p));
    return a;
}
__device__ __forceinline__ void cp16(uint32_t s, const void* g) {
    asm volatile("cp.async.cg.shared.global [%0], [%1], 16;" :: "r"(s), "l"(g));
}
__device__ __forceinline__ void cp_commit() {
    asm volatile("cp.async.commit_group;");
}
template <int N>
__device__ __forceinline__ void cp_wait() {
    asm volatile("cp.async.wait_group %0;" :: "n"(N));
}
__device__ __forceinline__ void ldsm4(uint32_t& r0, uint32_t& r1, uint32_t& r2, uint32_t& r3, uint32_t addr) {
    asm volatile("ldmatrix.sync.aligned.m8n8.x4.shared.b16 {%0,%1,%2,%3}, [%4];"
                 : "=r"(r0), "=r"(r1), "=r"(r2), "=r"(r3) : "r"(addr));
}
__device__ __forceinline__ void mma16816(float* d, const uint32_t* a, const uint32_t* b) {
    asm volatile(
        "mma.sync.aligned.m16n8k16.row.col.f32.bf16.bf16.f32 "
        "{%0,%1,%2,%3}, {%4,%5,%6,%7}, {%8,%9}, {%0,%1,%2,%3};"
        : "+f"(d[0]), "+f"(d[1]), "+f"(d[2]), "+f"(d[3])
        : "r"(a[0]), "r"(a[1]), "r"(a[2]), "r"(a[3]), "r"(b[0]), "r"(b[1]));
}

// ================= split/convert kernels =================
__global__ void split_A_kernel(const float* __restrict__ X, __nv_bfloat16* __restrict__ S, int M, int K) {
    int i = blockIdx.x * 256 + threadIdx.x;
    if (i >= M * K) return;
    int n = i / K, k = i - n * K;
    float v = X[i];
    __nv_bfloat16 hi = __float2bfloat16(v);
    __nv_bfloat16 lo = __float2bfloat16(v - __bfloat162float(hi));
    size_t b = (size_t)n * 3 * K;
    S[b + k] = hi; S[b + K + k] = hi; S[b + 2 * K + k] = lo;
}
// all four decoder weights in one launch (index-range dispatch)
__global__ void split_B4_kernel(const float* __restrict__ W1, const float* __restrict__ W2,
                                const float* __restrict__ W3, const float* __restrict__ W4,
                                __nv_bfloat16* __restrict__ S1, __nv_bfloat16* __restrict__ S2,
                                __nv_bfloat16* __restrict__ S3, __nv_bfloat16* __restrict__ S4)
{
    int i = blockIdx.x * 256 + threadIdx.x;
    const float* W; __nv_bfloat16* S; int K;
    if (i < 131072)            { W = W1; S = S1; K = 512;  }
    else if (i < 196608)       { W = W2; S = S2; K = 256;  i -= 131072; }
    else if (i < 327680)       { W = W3; S = S3; K = 256;  i -= 196608; }
    else if (i < 852000 && i < 851968) { W = W4; S = S4; K = 512; i -= 327680; }
    else return;
    int n = i / K, k = i - n * K;
    float v = W[(size_t)n * K + k];
    __nv_bfloat16 hi = __float2bfloat16(v);
    __nv_bfloat16 lo = __float2bfloat16(v - __bfloat162float(hi));
    size_t b = (size_t)n * 3 * K;
    S[b + k] = hi; S[b + K + k] = lo; S[b + 2 * K + k] = hi;
}
__global__ void repack_split_W_kernel(const float* __restrict__ W, __nv_bfloat16* __restrict__ S) {
    int i = blockIdx.x * 256 + threadIdx.x;   // 512*1024
    int n = i >> 10, f = i & 1023;
    int h = n >> 6, d = n & 63;
    float v = W[h * 65536 + f * 64 + d];
    __nv_bfloat16 hi = __float2bfloat16(v);
    __nv_bfloat16 lo = __float2bfloat16(v - __bfloat162float(hi));
    size_t b = (size_t)n * 3072;
    S[b + f] = hi; S[b + 1024 + f] = lo; S[b + 2048 + f] = hi;
}

// ================= mma.sync bf16 GEMM, 3-stage cp.async, swizzled smem ===========
// C[M,N] = act(A'[M,Kp] @ B'[N,Kp]^T + bias). Tile 64 x 128, 8 warps (warp 32x32),
// BK=32. Smem 36.9KB static -> 2-3 CTAs/SM resident for cross-CTA latency hiding.
template <int RELU, int WF32, int WSPLIT>
__global__ __launch_bounds__(256) void gemm_mma(
    const __nv_bfloat16* __restrict__ A, const __nv_bfloat16* __restrict__ B,
    const float* __restrict__ bias, float* __restrict__ Cf,
    __nv_bfloat16* __restrict__ Cs, int M, int N, int Kp)
{
    constexpr int TM = 64;
    constexpr int MI = 2;
    __shared__ __align__(16) __nv_bfloat16 sAb[3 * TM * 32];
    __shared__ __align__(16) __nv_bfloat16 sBb[3 * 128 * 32];

    const int tid  = threadIdx.x;
    const int warp = tid >> 5;
    const int lane = tid & 31;
    const int m0 = blockIdx.y * TM;
    const int n0 = blockIdx.x * 128;
    const int wm = (warp & 1) * 32;
    const int wn = (warp >> 1) * 32;
    const uint32_t baseA = smem_u32(sAb);
    const uint32_t baseB = smem_u32(sBb);

    float acc[MI][4][4];
    #pragma unroll
    for (int i = 0; i < MI; i++)
        #pragma unroll
        for (int j = 0; j < 4; j++)
            #pragma unroll
            for (int k = 0; k < 4; k++) acc[i][j][k] = 0.0f;

    const int NC = Kp >> 5;

    auto load_chunk = [&](int c, int s) {
        {   // B: 128 rows x 32 cols
            int r = tid >> 1, kb = (tid & 1) * 2;
            const __nv_bfloat16* gb = B + (size_t)(n0 + r) * Kp + c * 32;
            uint32_t rowbase = baseB + s * 128 * 64 + r * 64;
            uint32_t sw = ((r >> 1) & 3);
            cp16(rowbase + ((kb    ) ^ sw) * 16, gb + kb * 8);
            cp16(rowbase + ((kb + 1) ^ sw) * 16, gb + (kb + 1) * 8);
        }
        {   // A: 64 rows x 32 cols
            int r = tid >> 2, ks = tid & 3;
            const __nv_bfloat16* ga = A + (size_t)(m0 + r) * Kp + c * 32;
            uint32_t rowbase = baseA + s * TM * 64 + r * 64;
            cp16(rowbase + (ks ^ ((r >> 1) & 3)) * 16, ga + ks * 8);
        }
    };

    load_chunk(0, 0); cp_commit();
    load_chunk(1, 1); cp_commit();

    for (int c = 0; c < NC; c++) {
        const int st = c % 3;
        cp_wait<1>();
        __syncthreads();
        if (c + 2 < NC) load_chunk(c + 2, (c + 2) % 3);
        cp_commit();

        #pragma unroll
        for (int ks = 0; ks < 2; ks++) {
            uint32_t af[MI][4];
            #pragma unroll
            for (int mi = 0; mi < MI; mi++) {
                int row = wm + mi * 16 + (lane & 15);
                int kseg = ks * 2 + (lane >> 4);
                uint32_t addr = baseA + st * TM * 64 + row * 64
                              + (kseg ^ ((row >> 1) & 3)) * 16;
                ldsm4(af[mi][0], af[mi][1], af[mi][2], af[mi][3], addr);
            }
            uint32_t bf[4][2];
            #pragma unroll
            for (int ng = 0; ng < 2; ng++) {
                uint32_t r0, r1, r2, r3;
                int row = wn + ng * 16 + (lane & 15);
                int kseg = ks * 2 + (lane >> 4);
                uint32_t addr = baseB + st * 128 * 64 + row * 64
                              + (kseg ^ ((row >> 1) & 3)) * 16;
                ldsm4(r0, r1, r2, r3, addr);
                bf[ng * 2 + 0][0] = r0; bf[ng * 2 + 0][1] = r2;
                bf[ng * 2 + 1][0] = r1; bf[ng * 2 + 1][1] = r3;
            }
            #pragma unroll
            for (int mi = 0; mi < MI; mi++)
                #pragma unroll
                for (int nj = 0; nj < 4; nj++)
                    mma16816(acc[mi][nj], af[mi], bf[nj]);
        }
    }

    // ---- epilogue ----
    const int g = lane >> 2, t = lane & 3;
    #pragma unroll
    for (int mi = 0; mi < MI; mi++) {
        #pragma unroll
        for (int nj = 0; nj < 4; nj++) {
            int gr0 = m0 + wm + mi * 16 + g;
            int gc0 = n0 + wn + nj * 8 + 2 * t;
            #pragma unroll
            for (int hh = 0; hh < 2; hh++) {
                int gm = gr0 + hh * 8;
                #pragma unroll
                for (int ww = 0; ww < 2; ww++) {
                    int gc = gc0 + ww;
                    float v = acc[mi][nj][hh * 2 + ww];
                    if (bias) v += bias[gc];
                    if (RELU) v = fmaxf(v, 0.0f);
                    if (WF32) Cf[(size_t)gm * N + gc] = v;
                    if (WSPLIT) {
                        __nv_bfloat16 hi = __float2bfloat16(v);
                        __nv_bfloat16 lo = __float2bfloat16(v - __bfloat162float(hi));
                        size_t bo = (size_t)gm * 3 * N;
                        Cs[bo + gc] = hi; Cs[bo + N + gc] = hi; Cs[bo + 2 * N + gc] = lo;
                    }
                }
            }
        }
    }
}

// ================= e_src / e_dst =================
__global__ void esrc_kernel(const float* __restrict__ Wh,
                            const float* __restrict__ a1, const float* __restrict__ a2,
                            float* __restrict__ es, float* __restrict__ ed)
{
    int lane = threadIdx.x & 31;
    int h = threadIdx.x >> 5;
    int n = blockIdx.x;
    const float* wr = Wh + (size_t)n * 512 + h * 64;
    float w0 = wr[lane], w1 = wr[lane + 32];
    float s1 = w0 * a1[h * 64 + lane] + w1 * a1[h * 64 + lane + 32];
    float s2 = w0 * a2[h * 64 + lane] + w1 * a2[h * 64 + lane + 32];
    #pragma unroll
    for (int o = 16; o > 0; o >>= 1) {
        s1 += __shfl_xor_sync(0xffffffffu, s1, o);
        s2 += __shfl_xor_sync(0xffffffffu, s2, o);
    }
    if (lane == 0) { es[h * 4096 + n] = s1; ed[h * 4096 + n] = s2; }
}

// ================= sparse softmax attention + aggregate + elu (+split write) =================
__global__ __launch_bounds__(256) void attn_kernel(
    const float* __restrict__ adj, const float* __restrict__ Wh,
    const float* __restrict__ es,  const float* __restrict__ ed,
    __nv_bfloat16* __restrict__ encs)
{
    __shared__ int   s_idx[MAXNB];
    __shared__ float s_att[8][MAXNB];
    __shared__ int   s_wsum[8];
    __shared__ int   s_cnt;

    const int n    = blockIdx.x;
    const int t    = threadIdx.x;
    const int lane = t & 31;
    const int wid  = t >> 5;

    int local[16];
    int lc = 0;
    const float4* row4 = (const float4*)(adj + (size_t)n * 4096);
    #pragma unroll
    for (int i = 0; i < 4; i++) {
        float4 v = row4[i * 256 + t];
        int c = (i * 256 + t) * 4;
        if (v.x > 0.0f) local[lc++] = c + 0;
        if (v.y > 0.0f) local[lc++] = c + 1;
        if (v.z > 0.0f) local[lc++] = c + 2;
        if (v.w > 0.0f) local[lc++] = c + 3;
    }
    int incl = lc;
    #pragma unroll
    for (int o = 1; o < 32; o <<= 1) {
        int v = __shfl_up_sync(0xffffffffu, incl, o);
        if (lane >= o) incl += v;
    }
    if (lane == 31) s_wsum[wid] = incl;
    __syncthreads();
    int wofs = 0;
    #pragma unroll
    for (int w = 0; w < 8; w++) if (w < wid) wofs += s_wsum[w];
    int pos = wofs + incl - lc;
    for (int j = 0; j < lc; j++)
        if (pos + j < MAXNB) s_idx[pos + j] = local[j];
    if (t == 255) s_cnt = wofs + incl;
    __syncthreads();
    int cnt = s_cnt;
    if (cnt > MAXNB) cnt = MAXNB;

    const int h = wid;
    const float esv = es[h * 4096 + n];
    float mx = -1e30f;
    for (int m = lane; m < cnt; m += 32) {
        int j = s_idx[m];
        float z = esv + ed[h * 4096 + j];
        z = (z > 0.0f) ? z : LRELU_ALPHA * z;
        s_att[h][m] = z;
        mx = fmaxf(mx, z);
    }
    #pragma unroll
    for (int o = 16; o > 0; o >>= 1)
        mx = fmaxf(mx, __shfl_xor_sync(0xffffffffu, mx, o));
    __syncwarp();
    float sum = 0.0f;
    for (int m = lane; m < cnt; m += 32) {
        float p = __expf(s_att[h][m] - mx);
        s_att[h][m] = p;
        sum += p;
    }
    #pragma unroll
    for (int o = 16; o > 0; o >>= 1)
        sum += __shfl_xor_sync(0xffffffffu, sum, o);
    __syncwarp();
    float inv = 1.0f / sum;

    // aggregate, unrolled x4 for load batching (L2-latency bound gather)
    float acc0 = 0.0f, acc1 = 0.0f;
    int m = 0;
    for (; m + 4 <= cnt; m += 4) {
        int j0 = s_idx[m], j1 = s_idx[m + 1], j2 = s_idx[m + 2], j3 = s_idx[m + 3];
        float a0 = s_att[h][m], a1v = s_att[h][m + 1], a2v = s_att[h][m + 2], a3 = s_att[h][m + 3];
        const float* w0 = Wh + (size_t)j0 * 512 + h * 64;
        const float* w1 = Wh + (size_t)j1 * 512 + h * 64;
        const float* w2 = Wh + (size_t)j2 * 512 + h * 64;
        const float* w3 = Wh + (size_t)j3 * 512 + h * 64;
        float p00 = w0[lane], p01 = w0[lane + 32];
        float p10 = w1[lane], p11 = w1[lane + 32];
        float p20 = w2[lane], p21 = w2[lane + 32];
        float p30 = w3[lane], p31 = w3[lane + 32];
        acc0 += a0 * p00; acc1 += a0 * p01;
        acc0 += a1v * p10; acc1 += a1v * p11;
        acc0 += a2v * p20; acc1 += a2v * p21;
        acc0 += a3 * p30; acc1 += a3 * p31;
    }
    for (; m < cnt; m++) {
        int j   = s_idx[m];
        float a = s_att[h][m];
        const float* wr = Wh + (size_t)j * 512 + h * 64;
        acc0 += a * wr[lane];
        acc1 += a * wr[lane + 32];
    }
    acc0 *= inv;
    acc1 *= inv;
    acc0 = (acc0 > 0.0f) ? acc0 : (__expf(acc0) - 1.0f);
    acc1 = (acc1 > 0.0f) ? acc1 : (__expf(acc1) - 1.0f);

    size_t bo = (size_t)n * 1536;
    int c0 = h * 64 + lane, c1 = c0 + 32;
    __nv_bfloat16 h0 = __float2bfloat16(acc0);
    __nv_bfloat16 l0 = __float2bfloat16(acc0 - __bfloat162float(h0));
    __nv_bfloat16 h1 = __float2bfloat16(acc1);
    __nv_bfloat16 l1 = __float2bfloat16(acc1 - __bfloat162float(h1));
    encs[bo + c0] = h0;        encs[bo + c1] = h1;
    encs[bo + 512 + c0] = h0;  encs[bo + 512 + c1] = h1;
    encs[bo + 1024 + c0] = l0; encs[bo + 1024 + c1] = l1;
}

// ================= launch (nothing but kernel launches + symbol lookups) =========
extern "C" void kernel_launch(void* const* d_in, const int* in_sizes, int n_in,
                              void* d_out, int out_size)
{
    const float* x   = (const float*)d_in[0];
    const float* adj = (const float*)d_in[1];
    const float* W   = (const float*)d_in[2];
    const float* a1  = (const float*)d_in[3];
    const float* a2  = (const float*)d_in[4];
    const float* W1  = (const float*)d_in[5];
    const float* b1  = (const float*)d_in[6];
    const float* W2  = (const float*)d_in[7];
    const float* b2  = (const float*)d_in[8];
    const float* W3  = (const float*)d_in[9];
    const float* b3  = (const float*)d_in[10];
    const float* W4  = (const float*)d_in[11];
    const float* b4  = (const float*)d_in[12];
    float* out = (float*)d_out;

    __nv_bfloat16 *xs, *Wes, *encs, *W1s, *W2s, *W3s, *W4s, *h1s, *h2s, *h3s;
    float *Wh, *es, *ed;
    cudaGetSymbolAddress((void**)&xs, g_xs);
    cudaGetSymbolAddress((void**)&Wes, g_Wes);
    cudaGetSymbolAddress((void**)&Wh, g_Wh);
    cudaGetSymbolAddress((void**)&es, g_es);
    cudaGetSymbolAddress((void**)&ed, g_ed);
    cudaGetSymbolAddress((void**)&encs, g_encs);
    cudaGetSymbolAddress((void**)&W1s, g_W1s);
    cudaGetSymbolAddress((void**)&W2s, g_W2s);
    cudaGetSymbolAddress((void**)&W3s, g_W3s);
    cudaGetSymbolAddress((void**)&W4s, g_W4s);
    cudaGetSymbolAddress((void**)&h1s, g_h1s);
    cudaGetSymbolAddress((void**)&h2s, g_h2s);
    cudaGetSymbolAddress((void**)&h3s, g_h3s);

    // conversions
    split_A_kernel<<<(4096 * 1024 + 255) / 256, 256>>>(x, xs, 4096, 1024);
    repack_split_W_kernel<<<(512 * 1024) / 256, 256>>>(W, Wes);
    split_B4_kernel<<<(851968 + 255) / 256, 256>>>(W1, W2, W3, W4, W1s, W2s, W3s, W4s);

    // encoder GEMM: Wh = x @ Wenc   (M=4096, N=512, Kp=3072)
    gemm_mma<0, 1, 0><<<dim3(4, 64), 256>>>(xs, Wes, nullptr, Wh, nullptr, 4096, 512, 3072);
    esrc_kernel<<<4096, 256>>>(Wh, a1, a2, es, ed);
    attn_kernel<<<4096, 256>>>(adj, Wh, es, ed, encs);

    // decoder
    gemm_mma<1, 0, 1><<<dim3(2, 64), 256>>>(encs, W1s, b1, nullptr, h1s, 4096, 256, 1536);
    gemm_mma<1, 0, 1><<<dim3(2, 64), 256>>>(h1s,  W2s, b2, nullptr, h2s, 4096, 256, 768);
    gemm_mma<1, 0, 1><<<dim3(4, 64), 256>>>(h2s, W3s, b3, nullptr, h3s, 4096, 512, 768);
    gemm_mma<0, 1, 0><<<dim3(8, 64), 256>>>(h3s, W4s, b4, out, nullptr, 4096, 1024, 1536);
}

// round 8
// speedup vs baseline: 1.6489x; 1.0135x over previous
#include <cuda_runtime.h>
#include <cuda_bf16.h>
#include <cstdint>
#include <math.h>

#define LRELU_ALPHA 0.2f
#define MAXNB 256

// ================= scratch (__device__ globals; no allocation) =================
__device__ __align__(256) __nv_bfloat16 g_xs  [4096 * 3072];  // x split  [hi|hi|lo]
__device__ __align__(256) __nv_bfloat16 g_Wes [512 * 3072];   // enc W split [hi|lo|hi]
__device__ __align__(256) float         g_Wh  [4096 * 512];
__device__ __align__(256) float         g_es  [8 * 4096];
__device__ __align__(256) float         g_ed  [8 * 4096];
__device__ __align__(256) __nv_bfloat16 g_encs[4096 * 1536];
__device__ __align__(256) __nv_bfloat16 g_W1s [256 * 1536];
__device__ __align__(256) __nv_bfloat16 g_W2s [256 * 768];
__device__ __align__(256) __nv_bfloat16 g_W3s [512 * 768];
__device__ __align__(256) __nv_bfloat16 g_W4s [1024 * 1536];
__device__ __align__(256) __nv_bfloat16 g_h1s [4096 * 768];
__device__ __align__(256) __nv_bfloat16 g_h2s [4096 * 768];
__device__ __align__(256) __nv_bfloat16 g_h3s [4096 * 1536];

// ================= PTX helpers (plain sm_103-safe) =================
__device__ __forceinline__ uint32_t smem_u32(const void* p) {
    uint32_t a;
    asm("{ .reg .u64 t; cvta.to.shared.u64 t, %1; cvt.u32.u64 %0, t; }" : "=r"(a) : "l"(p));
    return a;
}
__device__ __forceinline__ void cp16(uint32_t s, const void* g) {
    asm volatile("cp.async.cg.shared.global [%0], [%1], 16;" :: "r"(s), "l"(g));
}
__device__ __forceinline__ void cp_commit() {
    asm volatile("cp.async.commit_group;");
}
template <int N>
__device__ __forceinline__ void cp_wait() {
    asm volatile("cp.async.wait_group %0;" :: "n"(N));
}
__device__ __forceinline__ void ldsm4(uint32_t& r0, uint32_t& r1, uint32_t& r2, uint32_t& r3, uint32_t addr) {
    asm volatile("ldmatrix.sync.aligned.m8n8.x4.shared.b16 {%0,%1,%2,%3}, [%4];"
                 : "=r"(r0), "=r"(r1), "=r"(r2), "=r"(r3) : "r"(addr));
}
__device__ __forceinline__ void mma16816(float* d, const uint32_t* a, const uint32_t* b) {
    asm volatile(
        "mma.sync.aligned.m16n8k16.row.col.f32.bf16.bf16.f32 "
        "{%0,%1,%2,%3}, {%4,%5,%6,%7}, {%8,%9}, {%0,%1,%2,%3};"
        : "+f"(d[0]), "+f"(d[1]), "+f"(d[2]), "+f"(d[3])
        : "r"(a[0]), "r"(a[1]), "r"(a[2]), "r"(a[3]), "r"(b[0]), "r"(b[1]));
}

// ================= split/convert kernels =================
__global__ void split_A_kernel(const float* __restrict__ X, __nv_bfloat16* __restrict__ S, int M, int K) {
    int i = blockIdx.x * 256 + threadIdx.x;
    if (i >= M * K) return;
    int n = i / K, k = i - n * K;
    float v = X[i];
    __nv_bfloat16 hi = __float2bfloat16(v);
    __nv_bfloat16 lo = __float2bfloat16(v - __bfloat162float(hi));
    size_t b = (size_t)n * 3 * K;
    S[b + k] = hi; S[b + K + k] = hi; S[b + 2 * K + k] = lo;
}
// all four decoder weights in one launch (index-range dispatch)
__global__ void split_B4_kernel(const float* __restrict__ W1, const float* __restrict__ W2,
                                const float* __restrict__ W3, const float* __restrict__ W4,
                                __nv_bfloat16* __restrict__ S1, __nv_bfloat16* __restrict__ S2,
                                __nv_bfloat16* __restrict__ S3, __nv_bfloat16* __restrict__ S4)
{
    int i = blockIdx.x * 256 + threadIdx.x;
    const float* W; __nv_bfloat16* S; int K;
    if (i < 131072)       { W = W1; S = S1; K = 512; }
    else if (i < 196608)  { W = W2; S = S2; K = 256; i -= 131072; }
    else if (i < 327680)  { W = W3; S = S3; K = 256; i -= 196608; }
    else if (i < 851968)  { W = W4; S = S4; K = 512; i -= 327680; }
    else return;
    int n = i / K, k = i - n * K;
    float v = W[(size_t)n * K + k];
    __nv_bfloat16 hi = __float2bfloat16(v);
    __nv_bfloat16 lo = __float2bfloat16(v - __bfloat162float(hi));
    size_t b = (size_t)n * 3 * K;
    S[b + k] = hi; S[b + K + k] = lo; S[b + 2 * K + k] = hi;
}
__global__ void repack_split_W_kernel(const float* __restrict__ W, __nv_bfloat16* __restrict__ S) {
    int i = blockIdx.x * 256 + threadIdx.x;   // 512*1024
    int n = i >> 10, f = i & 1023;
    int h = n >> 6, d = n & 63;
    float v = W[h * 65536 + f * 64 + d];
    __nv_bfloat16 hi = __float2bfloat16(v);
    __nv_bfloat16 lo = __float2bfloat16(v - __bfloat162float(hi));
    size_t b = (size_t)n * 3072;
    S[b + f] = hi; S[b + 1024 + f] = lo; S[b + 2048 + f] = hi;
}

// ================= mma.sync bf16 GEMM, 4-stage cp.async, swizzled smem ===========
// C[M,N] = act(A'[M,Kp] @ B'[N,Kp]^T + bias). Tile 64 x 128, 8 warps (warp 32x32),
// BK=32, 4 stages (48KB static smem exactly) with wait_group<2> -> 3-chunk
// lookahead (~570cyc) to cover DRAM latency. ldmatrix addresses precomputed.
template <int RELU, int WF32, int WSPLIT>
__global__ __launch_bounds__(256) void gemm_mma(
    const __nv_bfloat16* __restrict__ A, const __nv_bfloat16* __restrict__ B,
    const float* __restrict__ bias, float* __restrict__ Cf,
    __nv_bfloat16* __restrict__ Cs, int M, int N, int Kp)
{
    constexpr int TM = 64;
    constexpr int MI = 2;
    __shared__ __align__(16) __nv_bfloat16 sAb[4 * TM * 32];   // 16 KB
    __shared__ __align__(16) __nv_bfloat16 sBb[4 * 128 * 32];  // 32 KB

    const int tid  = threadIdx.x;
    const int warp = tid >> 5;
    const int lane = tid & 31;
    const int m0 = blockIdx.y * TM;
    const int n0 = blockIdx.x * 128;
    const int wm = (warp & 1) * 32;
    const int wn = (warp >> 1) * 32;
    const uint32_t baseA = smem_u32(sAb);
    const uint32_t baseB = smem_u32(sBb);

    // precomputed ldmatrix addresses (stage 0); inner loop adds stage offset
    uint32_t aA[MI][2], aB[2][2];
    #pragma unroll
    for (int mi = 0; mi < MI; mi++)
        #pragma unroll
        for (int ks = 0; ks < 2; ks++) {
            int row = wm + mi * 16 + (lane & 15);
            int kseg = ks * 2 + (lane >> 4);
            aA[mi][ks] = baseA + row * 64 + ((kseg ^ ((row >> 1) & 3)) * 16);
        }
    #pragma unroll
    for (int ng = 0; ng < 2; ng++)
        #pragma unroll
        for (int ks = 0; ks < 2; ks++) {
            int row = wn + ng * 16 + (lane & 15);
            int kseg = ks * 2 + (lane >> 4);
            aB[ng][ks] = baseB + row * 64 + ((kseg ^ ((row >> 1) & 3)) * 16);
        }

    float acc[MI][4][4];
    #pragma unroll
    for (int i = 0; i < MI; i++)
        #pragma unroll
        for (int j = 0; j < 4; j++)
            #pragma unroll
            for (int k = 0; k < 4; k++) acc[i][j][k] = 0.0f;

    const int NC = Kp >> 5;

    auto load_chunk = [&](int c, int s) {
        {   // B: 128 rows x 32 cols
            int r = tid >> 1, kb = (tid & 1) * 2;
            const __nv_bfloat16* gb = B + (size_t)(n0 + r) * Kp + c * 32;
            uint32_t rowbase = baseB + s * 8192 + r * 64;
            uint32_t sw = ((r >> 1) & 3);
            cp16(rowbase + ((kb    ) ^ sw) * 16, gb + kb * 8);
            cp16(rowbase + ((kb + 1) ^ sw) * 16, gb + (kb + 1) * 8);
        }
        {   // A: 64 rows x 32 cols
            int r = tid >> 2, ks = tid & 3;
            const __nv_bfloat16* ga = A + (size_t)(m0 + r) * Kp + c * 32;
            uint32_t rowbase = baseA + s * 4096 + r * 64;
            cp16(rowbase + (ks ^ ((r >> 1) & 3)) * 16, ga + ks * 8);
        }
    };

    load_chunk(0, 0); cp_commit();
    load_chunk(1, 1); cp_commit();
    load_chunk(2, 2); cp_commit();

    for (int c = 0; c < NC; c++) {
        const int st = c & 3;
        cp_wait<2>();            // chunk c complete (3 groups in flight max)
        __syncthreads();
        if (c + 3 < NC) load_chunk(c + 3, (c + 3) & 3);
        cp_commit();

        const uint32_t offA = st * 4096;
        const uint32_t offB = st * 8192;
        #pragma unroll
        for (int ks = 0; ks < 2; ks++) {
            uint32_t af[MI][4];
            #pragma unroll
            for (int mi = 0; mi < MI; mi++)
                ldsm4(af[mi][0], af[mi][1], af[mi][2], af[mi][3], aA[mi][ks] + offA);
            uint32_t bf[4][2];
            #pragma unroll
            for (int ng = 0; ng < 2; ng++) {
                uint32_t r0, r1, r2, r3;
                ldsm4(r0, r1, r2, r3, aB[ng][ks] + offB);
                bf[ng * 2 + 0][0] = r0; bf[ng * 2 + 0][1] = r2;
                bf[ng * 2 + 1][0] = r1; bf[ng * 2 + 1][1] = r3;
            }
            #pragma unroll
            for (int mi = 0; mi < MI; mi++)
                #pragma unroll
                for (int nj = 0; nj < 4; nj++)
                    mma16816(acc[mi][nj], af[mi], bf[nj]);
        }
    }

    // ---- epilogue ----
    const int g = lane >> 2, t = lane & 3;
    #pragma unroll
    for (int mi = 0; mi < MI; mi++) {
        #pragma unroll
        for (int nj = 0; nj < 4; nj++) {
            int gr0 = m0 + wm + mi * 16 + g;
            int gc0 = n0 + wn + nj * 8 + 2 * t;
            #pragma unroll
            for (int hh = 0; hh < 2; hh++) {
                int gm = gr0 + hh * 8;
                #pragma unroll
                for (int ww = 0; ww < 2; ww++) {
                    int gc = gc0 + ww;
                    float v = acc[mi][nj][hh * 2 + ww];
                    if (bias) v += bias[gc];
                    if (RELU) v = fmaxf(v, 0.0f);
                    if (WF32) Cf[(size_t)gm * N + gc] = v;
                    if (WSPLIT) {
                        __nv_bfloat16 hi = __float2bfloat16(v);
                        __nv_bfloat16 lo = __float2bfloat16(v - __bfloat162float(hi));
                        size_t bo = (size_t)gm * 3 * N;
                        Cs[bo + gc] = hi; Cs[bo + N + gc] = hi; Cs[bo + 2 * N + gc] = lo;
                    }
                }
            }
        }
    }
}

// ================= e_src / e_dst =================
__global__ void esrc_kernel(const float* __restrict__ Wh,
                            const float* __restrict__ a1, const float* __restrict__ a2,
                            float* __restrict__ es, float* __restrict__ ed)
{
    int lane = threadIdx.x & 31;
    int h = threadIdx.x >> 5;
    int n = blockIdx.x;
    const float* wr = Wh + (size_t)n * 512 + h * 64;
    float w0 = wr[lane], w1 = wr[lane + 32];
    float s1 = w0 * a1[h * 64 + lane] + w1 * a1[h * 64 + lane + 32];
    float s2 = w0 * a2[h * 64 + lane] + w1 * a2[h * 64 + lane + 32];
    #pragma unroll
    for (int o = 16; o > 0; o >>= 1) {
        s1 += __shfl_xor_sync(0xffffffffu, s1, o);
        s2 += __shfl_xor_sync(0xffffffffu, s2, o);
    }
    if (lane == 0) { es[h * 4096 + n] = s1; ed[h * 4096 + n] = s2; }
}

// ================= sparse softmax attention + aggregate + elu (+split write) =================
__global__ __launch_bounds__(256) void attn_kernel(
    const float* __restrict__ adj, const float* __restrict__ Wh,
    const float* __restrict__ es,  const float* __restrict__ ed,
    __nv_bfloat16* __restrict__ encs)
{
    __shared__ int   s_idx[MAXNB];
    __shared__ float s_att[8][MAXNB];
    __shared__ int   s_wsum[8];
    __shared__ int   s_cnt;

    const int n    = blockIdx.x;
    const int t    = threadIdx.x;
    const int lane = t & 31;
    const int wid  = t >> 5;

    int local[16];
    int lc = 0;
    const float4* row4 = (const float4*)(adj + (size_t)n * 4096);
    #pragma unroll
    for (int i = 0; i < 4; i++) {
        float4 v = row4[i * 256 + t];
        int c = (i * 256 + t) * 4;
        if (v.x > 0.0f) local[lc++] = c + 0;
        if (v.y > 0.0f) local[lc++] = c + 1;
        if (v.z > 0.0f) local[lc++] = c + 2;
        if (v.w > 0.0f) local[lc++] = c + 3;
    }
    int incl = lc;
    #pragma unroll
    for (int o = 1; o < 32; o <<= 1) {
        int v = __shfl_up_sync(0xffffffffu, incl, o);
        if (lane >= o) incl += v;
    }
    if (lane == 31) s_wsum[wid] = incl;
    __syncthreads();
    int wofs = 0;
    #pragma unroll
    for (int w = 0; w < 8; w++) if (w < wid) wofs += s_wsum[w];
    int pos = wofs + incl - lc;
    for (int j = 0; j < lc; j++)
        if (pos + j < MAXNB) s_idx[pos + j] = local[j];
    if (t == 255) s_cnt = wofs + incl;
    __syncthreads();
    int cnt = s_cnt;
    if (cnt > MAXNB) cnt = MAXNB;

    const int h = wid;
    const float esv = es[h * 4096 + n];
    float mx = -1e30f;
    for (int m = lane; m < cnt; m += 32) {
        int j = s_idx[m];
        float z = esv + ed[h * 4096 + j];
        z = (z > 0.0f) ? z : LRELU_ALPHA * z;
        s_att[h][m] = z;
        mx = fmaxf(mx, z);
    }
    #pragma unroll
    for (int o = 16; o > 0; o >>= 1)
        mx = fmaxf(mx, __shfl_xor_sync(0xffffffffu, mx, o));
    __syncwarp();
    float sum = 0.0f;
    for (int m = lane; m < cnt; m += 32) {
        float p = __expf(s_att[h][m] - mx);
        s_att[h][m] = p;
        sum += p;
    }
    #pragma unroll
    for (int o = 16; o > 0; o >>= 1)
        sum += __shfl_xor_sync(0xffffffffu, sum, o);
    __syncwarp();
    float inv = 1.0f / sum;

    float acc0 = 0.0f, acc1 = 0.0f;
    int m = 0;
    for (; m + 4 <= cnt; m += 4) {
        int j0 = s_idx[m], j1 = s_idx[m + 1], j2 = s_idx[m + 2], j3 = s_idx[m + 3];
        float a0 = s_att[h][m], a1v = s_att[h][m + 1], a2v = s_att[h][m + 2], a3 = s_att[h][m + 3];
        const float* w0 = Wh + (size_t)j0 * 512 + h * 64;
        const float* w1 = Wh + (size_t)j1 * 512 + h * 64;
        const float* w2 = Wh + (size_t)j2 * 512 + h * 64;
        const float* w3 = Wh + (size_t)j3 * 512 + h * 64;
        float p00 = w0[lane], p01 = w0[lane + 32];
        float p10 = w1[lane], p11 = w1[lane + 32];
        float p20 = w2[lane], p21 = w2[lane + 32];
        float p30 = w3[lane], p31 = w3[lane + 32];
        acc0 += a0 * p00; acc1 += a0 * p01;
        acc0 += a1v * p10; acc1 += a1v * p11;
        acc0 += a2v * p20; acc1 += a2v * p21;
        acc0 += a3 * p30; acc1 += a3 * p31;
    }
    for (; m < cnt; m++) {
        int j   = s_idx[m];
        float a = s_att[h][m];
        const float* wr = Wh + (size_t)j * 512 + h * 64;
        acc0 += a * wr[lane];
        acc1 += a * wr[lane + 32];
    }
    acc0 *= inv;
    acc1 *= inv;
    acc0 = (acc0 > 0.0f) ? acc0 : (__expf(acc0) - 1.0f);
    acc1 = (acc1 > 0.0f) ? acc1 : (__expf(acc1) - 1.0f);

    size_t bo = (size_t)n * 1536;
    int c0 = h * 64 + lane, c1 = c0 + 32;
    __nv_bfloat16 h0 = __float2bfloat16(acc0);
    __nv_bfloat16 l0 = __float2bfloat16(acc0 - __bfloat162float(h0));
    __nv_bfloat16 h1 = __float2bfloat16(acc1);
    __nv_bfloat16 l1 = __float2bfloat16(acc1 - __bfloat162float(h1));
    encs[bo + c0] = h0;        encs[bo + c1] = h1;
    encs[bo + 512 + c0] = h0;  encs[bo + 512 + c1] = h1;
    encs[bo + 1024 + c0] = l0; encs[bo + 1024 + c1] = l1;
}

// ================= launch (nothing but kernel launches + symbol lookups) =========
extern "C" void kernel_launch(void* const* d_in, const int* in_sizes, int n_in,
                              void* d_out, int out_size)
{
    const float* x   = (const float*)d_in[0];
    const float* adj = (const float*)d_in[1];
    const float* W   = (const float*)d_in[2];
    const float* a1  = (const float*)d_in[3];
    const float* a2  = (const float*)d_in[4];
    const float* W1  = (const float*)d_in[5];
    const float* b1  = (const float*)d_in[6];
    const float* W2  = (const float*)d_in[7];
    const float* b2  = (const float*)d_in[8];
    const float* W3  = (const float*)d_in[9];
    const float* b3  = (const float*)d_in[10];
    const float* W4  = (const float*)d_in[11];
    const float* b4  = (const float*)d_in[12];
    float* out = (float*)d_out;

    __nv_bfloat16 *xs, *Wes, *encs, *W1s, *W2s, *W3s, *W4s, *h1s, *h2s, *h3s;
    float *Wh, *es, *ed;
    cudaGetSymbolAddress((void**)&xs, g_xs);
    cudaGetSymbolAddress((void**)&Wes, g_Wes);
    cudaGetSymbolAddress((void**)&Wh, g_Wh);
    cudaGetSymbolAddress((void**)&es, g_es);
    cudaGetSymbolAddress((void**)&ed, g_ed);
    cudaGetSymbolAddress((void**)&encs, g_encs);
    cudaGetSymbolAddress((void**)&W1s, g_W1s);
    cudaGetSymbolAddress((void**)&W2s, g_W2s);
    cudaGetSymbolAddress((void**)&W3s, g_W3s);
    cudaGetSymbolAddress((void**)&W4s, g_W4s);
    cudaGetSymbolAddress((void**)&h1s, g_h1s);
    cudaGetSymbolAddress((void**)&h2s, g_h2s);
    cudaGetSymbolAddress((void**)&h3s, g_h3s);

    // conversions
    split_A_kernel<<<(4096 * 1024 + 255) / 256, 256>>>(x, xs, 4096, 1024);
    repack_split_W_kernel<<<(512 * 1024) / 256, 256>>>(W, Wes);
    split_B4_kernel<<<(851968 + 255) / 256, 256>>>(W1, W2, W3, W4, W1s, W2s, W3s, W4s);

    // encoder GEMM: Wh = x @ Wenc   (M=4096, N=512, Kp=3072)
    gemm_mma<0, 1, 0><<<dim3(4, 64), 256>>>(xs, Wes, nullptr, Wh, nullptr, 4096, 512, 3072);
    esrc_kernel<<<4096, 256>>>(Wh, a1, a2, es, ed);
    attn_kernel<<<4096, 256>>>(adj, Wh, es, ed, encs);

    // decoder
    gemm_mma<1, 0, 1><<<dim3(2, 64), 256>>>(encs, W1s, b1, nullptr, h1s, 4096, 256, 1536);
    gemm_mma<1, 0, 1><<<dim3(2, 64), 256>>>(h1s,  W2s, b2, nullptr, h2s, 4096, 256, 768);
    gemm_mma<1, 0, 1><<<dim3(4, 64), 256>>>(h2s, W3s, b3, nullptr, h3s, 4096, 512, 768);
    gemm_mma<0, 1, 0><<<dim3(8, 64), 256>>>(h3s, W4s, b4, out, nullptr, 4096, 1024, 1536);
}